// round 12
// baseline (speedup 1.0000x reference)
#include <cuda_runtime.h>

#define BB 16
#define SS 4096
#define HH 16
#define EE 64
#define SDIM 64
#define NW 127

// Scratch (device globals — no allocation allowed in kernel_launch)
__device__ float g_vs4[4*BB*HH*SDIM*EE]; // [q][b][h][j][e] partial column sums
__device__ float g_us[BB*HH*SDIM*EE];    // [b][h][i][e]    row sums (complete)
__device__ float g_rv[BB*SDIM*HH*EE];    // [b][k][h][e]    RxV
__device__ float g_ru[BB*SDIM*HH*EE];    // [b][k][h][e]    RxU
__device__ float g_zc[HH*SDIM];          // [h][k]          z conv (x64)

// ---------------------------------------------------------------------------
// Kernel 1: row/column sums of v viewed as (b, i, j, h, e), s = i*64+j.
// Grid = 1024: (bh, q) quarter; block covers 16 i-rows, ONE i-row per thread
// (warp w: i = q*16 + w*2 + sub, sub = half-warp). Grid now exceeds the
// 5-block/SM resource cap -> occ ~62% (vs 41% at grid 512). j in chunks of
// 8 keeps the per-thread LDG.128 batch at 8 (vloc[8] ~ 50 regs total).
// Half-warp pairs combine column partials via shfl_down(16); double-buffered
// 2x8KB stage, ONE barrier per chunk, reducer half alternates so the other
// half issues the next chunk's loads immediately. Row sums stay in registers.
// ---------------------------------------------------------------------------
__global__ __launch_bounds__(256, 5) void k_reduce(const float* __restrict__ v) {
    int bid = blockIdx.x;
    int bh = bid >> 2, q = bid & 3;
    int b = bh >> 4, h = bh & 15;
    int t = threadIdx.x;
    int e4 = t & 15, sub = (t >> 4) & 1, w = t >> 5;

    __shared__ float4 stage[2][8*8*16];   // [buf][w*8+jj][e4]  2 x 8KB... (8w*8jj*16e4)

    const float4* v4 = reinterpret_cast<const float4*>(v)
                     + (size_t)b*SS*(HH*EE/4) + h*(EE/4) + e4;

    int i = q*16 + w*2 + sub;            // this thread's single i-row
    float4 crow = make_float4(0.f,0.f,0.f,0.f);

    float* vs_dst = g_vs4 + (size_t)(q*BB*HH + bh)*SDIM*EE;

    #pragma unroll 1
    for (int jc = 0; jc < 8; ++jc) {
        float4 vloc[8];
        const float4* p0 = v4 + (size_t)(i*SDIM + jc*8)*(HH*EE/4);
        #pragma unroll
        for (int jj = 0; jj < 8; ++jj) {
            float4 a = __ldcs(p0 + (size_t)jj*(HH*EE/4));
            crow.x += a.x; crow.y += a.y; crow.z += a.z; crow.w += a.w;
            vloc[jj] = a;
        }
        // combine the two half-warps (sub 0/1 hold adjacent i-rows, same j/e)
        #pragma unroll
        for (int jj = 0; jj < 8; ++jj) {
            vloc[jj].x += __shfl_down_sync(0xffffffffu, vloc[jj].x, 16);
            vloc[jj].y += __shfl_down_sync(0xffffffffu, vloc[jj].y, 16);
            vloc[jj].z += __shfl_down_sync(0xffffffffu, vloc[jj].z, 16);
            vloc[jj].w += __shfl_down_sync(0xffffffffu, vloc[jj].w, 16);
        }
        if (sub == 0) {
            #pragma unroll
            for (int jj = 0; jj < 8; ++jj)
                stage[jc & 1][(w*8 + jj)*16 + e4] = vloc[jj];
        }
        __syncthreads();

        // Alternate which half reduces; the other half issues next-chunk loads.
        bool lower = (t < 128);
        if (lower == ((jc & 1) == 0)) {
            int tt = t & 127;
            int jj = tt >> 4, ee = tt & 15;
            float4 s = stage[jc & 1][jj*16 + ee];
            #pragma unroll
            for (int ww = 1; ww < 8; ++ww) {
                float4 x = stage[jc & 1][(ww*8 + jj)*16 + ee];
                s.x += x.x; s.y += x.y; s.z += x.z; s.w += x.w;
            }
            reinterpret_cast<float4*>(vs_dst + (jc*8 + jj)*EE)[ee] = s;
        }
    }

    // Row sum for this thread's i-row (complete: covered all 64 j).
    float4* us4 = reinterpret_cast<float4*>(g_us + (size_t)bh*SDIM*EE);
    us4[i*(EE/4) + e4] = crow;
}

// ---------------------------------------------------------------------------
// Kernel 2: 64-tap circular convolutions. Grid 512: 2 blocks per (b,h), each
// covering half the k range. Merges the 4 partial column-sum slices with
// float4 loads. b==0,kh==0 blocks also compute zc.
// ---------------------------------------------------------------------------
__global__ __launch_bounds__(256) void k_conv(const float* __restrict__ w,
                                              const float* __restrict__ o_) {
    int blk = blockIdx.x;
    int bh = blk >> 1, kh = blk & 1;
    int b = bh >> 4, h = bh & 15;
    int t = threadIdx.x;

    __shared__ float vs_s[SDIM*EE];
    __shared__ float us_s[SDIM*EE];
    __shared__ float w_s[NW];
    __shared__ float o_s[SDIM];

    const size_t base = (size_t)bh*SDIM*EE;
    const size_t slice4 = (size_t)BB*HH*SDIM*EE/4;
    {
        const float4* pa = reinterpret_cast<const float4*>(g_vs4 + base);
        const float4* pu = reinterpret_cast<const float4*>(g_us + base);
        float4* vsv = reinterpret_cast<float4*>(vs_s);
        float4* usv = reinterpret_cast<float4*>(us_s);
        #pragma unroll
        for (int r = 0; r < 4; ++r) {
            int idx = r*256 + t;
            float4 a = __ldg(pa + idx);
            float4 x = __ldg(pa + slice4 + idx);
            float4 y = __ldg(pa + 2*slice4 + idx);
            float4 z = __ldg(pa + 3*slice4 + idx);
            vsv[idx] = make_float4(a.x+x.x+y.x+z.x, a.y+x.y+y.y+z.y,
                                   a.z+x.z+y.z+z.z, a.w+x.w+y.w+z.w);
            usv[idx] = __ldg(pu + idx);
        }
    }
    if (t < NW) w_s[t] = w[h*NW + t];
    if (t >= 128 && t < 128 + SDIM) o_s[t - 128] = o_[t - 128];
    __syncthreads();

    if (b == 0 && kh == 0 && t < SDIM) {
        float acc = 0.f;
        #pragma unroll
        for (int j = 0; j < SDIM; ++j) {
            int idx = t + 64 - j;
            if (idx > 126) idx -= 127;
            acc += o_s[j] * w_s[idx];
        }
        g_zc[h*SDIM + t] = acc * 64.f;
    }

    int e = t & 63, g = t >> 6;
    #pragma unroll 1
    for (int k = kh*32 + g; k < kh*32 + 32; k += 4) {
        float rv = 0.f, ru = 0.f;
        #pragma unroll
        for (int j = 0; j < SDIM; ++j) {
            int idx = k + 64 - j;            // range [1,127]
            if (idx > 126) idx -= 127;       // 127 -> 0
            float wk = w_s[idx];
            rv += vs_s[j*EE + e] * wk;
            ru += us_s[j*EE + e] * wk;
        }
        size_t o = ((size_t)(b*SDIM + k)*HH + h)*EE + e;
        g_rv[o] = rv;
        g_ru[o] = ru;
    }
}

// ---------------------------------------------------------------------------
// Kernel 3: pbv[b, i*64+j, h, e] = RxV[...,j] + RxU[...,i].
// Blocks 0..1023: 8i x 8j tile; RxU rows in registers, each RxV row from L2
// serves 8 output rows; streaming stores for the 256MB write.
// Blocks 1024..1039: z_pb output from g_zc.
// ---------------------------------------------------------------------------
__global__ __launch_bounds__(256) void k_out(float* __restrict__ out) {
    int blk = blockIdx.x;
    int t = threadIdx.x;

    if (blk < 1024) {
        int b = blk >> 6;
        int itile = (blk >> 3) & 7;
        int jt = blk & 7;

        const float4* rub = reinterpret_cast<const float4*>(g_ru + (size_t)b*SDIM*HH*EE)
                          + (size_t)itile*8*(HH*EE/4) + t;
        const float4* rvb = reinterpret_cast<const float4*>(g_rv + (size_t)b*SDIM*HH*EE)
                          + (size_t)jt*8*(HH*EE/4) + t;
        float4* ob = reinterpret_cast<float4*>(out + (size_t)b*SS*HH*EE)
                   + ((size_t)itile*8*SDIM + jt*8)*(HH*EE/4) + t;

        float4 uu[8];
        #pragma unroll
        for (int m = 0; m < 8; ++m)
            uu[m] = __ldg(rub + m*(HH*EE/4));

        #pragma unroll 1
        for (int jj = 0; jj < 8; ++jj) {
            float4 vv = __ldg(rvb + jj*(HH*EE/4));
            #pragma unroll
            for (int m = 0; m < 8; ++m) {
                float4 o;
                o.x = vv.x + uu[m].x; o.y = vv.y + uu[m].y;
                o.z = vv.z + uu[m].z; o.w = vv.w + uu[m].w;
                __stcs(ob + ((size_t)m*SDIM + jj)*(HH*EE/4), o);
            }
        }
    } else {
        int zi = blk - 1024;            // 0..15 -> i = zi*4 .. +3
        __shared__ float zc[HH*SDIM];
        for (int idx = t; idx < HH*SDIM; idx += 256) zc[idx] = g_zc[idx];
        __syncthreads();

        float* o2 = out + (size_t)BB*SS*HH*EE;
        #pragma unroll
        for (int r = 0; r < 4; ++r) {
            int i = zi*4 + r;
            #pragma unroll
            for (int it = 0; it < 4; ++it) {
                int idx = it*256 + t;
                int j = idx >> 4, h = idx & 15;
                o2[(size_t)i*1024 + idx] = zc[h*SDIM + j] + zc[h*SDIM + i];
            }
        }
    }
}

extern "C" void kernel_launch(void* const* d_in, const int* in_sizes, int n_in,
                              void* d_out, int out_size) {
    const float* v  = (const float*)d_in[0];
    const float* w  = (const float*)d_in[1];
    const float* o_ = (const float*)d_in[2];
    float* out = (float*)d_out;

    k_reduce<<<BB*HH*4, 256>>>(v);
    k_conv  <<<BB*HH*2, 256>>>(w, o_);
    k_out   <<<1024 + 16, 256>>>(out);
}

// round 13
// speedup vs baseline: 1.0901x; 1.0901x over previous
#include <cuda_runtime.h>

#define BB 16
#define SS 4096
#define HH 16
#define EE 64
#define SDIM 64
#define NW 127

// Scratch (device globals — no allocation allowed in kernel_launch)
__device__ float g_vs2[2*BB*HH*SDIM*EE]; // [half][b][h][j][e] partial column sums
__device__ float g_us[BB*HH*SDIM*EE];    // [b][h][i][e]       row sums (complete)
__device__ float g_rv[BB*SDIM*HH*EE];    // [b][k][h][e]       RxV
__device__ float g_ru[BB*SDIM*HH*EE];    // [b][k][h][e]       RxU
__device__ float g_zc[HH*SDIM];          // [h][k]             z conv (x64)

// ---------------------------------------------------------------------------
// Kernel 1 (exact R5 config — measured 45.1us, 76.9% DRAM):
// Grid = 512: (bh, half). Block covers 32 i. Warp w owns i = half*32+w*4+sub*2
// +{0,1} (sub = half-warp). 16 LDG.128/thread per 8-j chunk; half-warp pairs
// combine column partials via shfl_down(16); lanes<16 stage 8-warp partials
// to a double-buffered 16KB stage. ONE barrier per chunk: the half of the
// block not reducing this chunk immediately issues the next chunk's loads.
// ---------------------------------------------------------------------------
__global__ __launch_bounds__(256) void k_reduce(const float* __restrict__ v) {
    int bid = blockIdx.x;
    int bh = bid >> 1, half = bid & 1;
    int b = bh >> 4, h = bh & 15;
    int t = threadIdx.x;
    int e4 = t & 15, sub = (t >> 4) & 1, w = t >> 5;

    __shared__ float4 stage[2][8*8*16];   // [buf][w*8+jj][e4]  2 x 16KB

    const float4* v4 = reinterpret_cast<const float4*>(v)
                     + (size_t)b*SS*(HH*EE/4) + h*(EE/4) + e4;

    int i0 = half*32 + w*4 + sub*2;
    float4 crow0 = make_float4(0.f,0.f,0.f,0.f);
    float4 crow1 = make_float4(0.f,0.f,0.f,0.f);

    float* vs_dst = g_vs2 + (size_t)(half*BB*HH + bh)*SDIM*EE;

    #pragma unroll 1
    for (int jc = 0; jc < 8; ++jc) {
        float4 vloc[8];
        const float4* p0 = v4 + (size_t)(i0*SDIM + jc*8)*(HH*EE/4);
        const float4* p1 = p0 + (size_t)SDIM*(HH*EE/4);
        #pragma unroll
        for (int jj = 0; jj < 8; ++jj) {
            float4 a = __ldcs(p0 + (size_t)jj*(HH*EE/4));
            float4 c = __ldcs(p1 + (size_t)jj*(HH*EE/4));
            crow0.x += a.x; crow0.y += a.y; crow0.z += a.z; crow0.w += a.w;
            crow1.x += c.x; crow1.y += c.y; crow1.z += c.z; crow1.w += c.w;
            vloc[jj] = make_float4(a.x + c.x, a.y + c.y, a.z + c.z, a.w + c.w);
        }
        // combine the two half-warps (sub 0/1 hold different i-pairs, same j/e)
        #pragma unroll
        for (int jj = 0; jj < 8; ++jj) {
            vloc[jj].x += __shfl_down_sync(0xffffffffu, vloc[jj].x, 16);
            vloc[jj].y += __shfl_down_sync(0xffffffffu, vloc[jj].y, 16);
            vloc[jj].z += __shfl_down_sync(0xffffffffu, vloc[jj].z, 16);
            vloc[jj].w += __shfl_down_sync(0xffffffffu, vloc[jj].w, 16);
        }
        if (sub == 0) {
            #pragma unroll
            for (int jj = 0; jj < 8; ++jj)
                stage[jc & 1][(w*8 + jj)*16 + e4] = vloc[jj];
        }
        __syncthreads();

        // Alternate which half reduces; the other half issues next-chunk loads.
        bool lower = (t < 128);
        if (lower == ((jc & 1) == 0)) {
            int tt = t & 127;
            int jj = tt >> 4, ee = tt & 15;
            float4 s = stage[jc & 1][jj*16 + ee];
            #pragma unroll
            for (int ww = 1; ww < 8; ++ww) {
                float4 x = stage[jc & 1][(ww*8 + jj)*16 + ee];
                s.x += x.x; s.y += x.y; s.z += x.z; s.w += x.w;
            }
            reinterpret_cast<float4*>(vs_dst + (jc*8 + jj)*EE)[ee] = s;
        }
    }

    // Row sums (complete: thread covered all 64 j for its 2 i's).
    float4* us4 = reinterpret_cast<float4*>(g_us + (size_t)bh*SDIM*EE);
    us4[(i0    )*(EE/4) + e4] = crow0;
    us4[(i0 + 1)*(EE/4) + e4] = crow1;
}

// ---------------------------------------------------------------------------
// Kernel 2: register-tiled circular convolutions. Grid 512: (bh, kh).
// Thread (e4 = t&15, kg = t>>4) accumulates a 2k x 4e x {rv,ru} register tile:
// per j-iteration 2 LDS.128 (vs/us, kg-pair broadcast) + 2 scalar w loads
// feed 16 FMAs (vs 2 LDS / 2 FMA before). w_s[127] = w_s[0] removes the
// wrap branch. Plain stores keep rv/ru L2-resident for k_out.
// ---------------------------------------------------------------------------
__global__ __launch_bounds__(256) void k_conv(const float* __restrict__ w,
                                              const float* __restrict__ o_) {
    int blk = blockIdx.x;
    int bh = blk >> 1, kh = blk & 1;
    int b = bh >> 4, h = bh & 15;
    int t = threadIdx.x;

    __shared__ float4 vs_s[SDIM*16];   // [j][e4]
    __shared__ float4 us_s[SDIM*16];
    __shared__ float w_s[NW+1];
    __shared__ float o_s[SDIM];

    const size_t base = (size_t)bh*SDIM*EE;
    const size_t slice4 = (size_t)BB*HH*SDIM*EE/4;
    {
        const float4* pa = reinterpret_cast<const float4*>(g_vs2 + base);
        const float4* pu = reinterpret_cast<const float4*>(g_us + base);
        #pragma unroll
        for (int r = 0; r < 4; ++r) {
            int idx = r*256 + t;
            float4 x = __ldg(pa + idx), y = __ldg(pa + slice4 + idx);
            vs_s[idx] = make_float4(x.x+y.x, x.y+y.y, x.z+y.z, x.w+y.w);
            us_s[idx] = __ldg(pu + idx);
        }
    }
    if (t < NW) w_s[t] = w[h*NW + t];
    if (t == NW) w_s[NW] = w[h*NW];          // pad: w_s[127] = w_s[0]
    if (t >= 128 && t < 128 + SDIM) o_s[t - 128] = o_[t - 128];
    __syncthreads();

    if (b == 0 && kh == 0 && t < SDIM) {
        float acc = 0.f;
        #pragma unroll
        for (int j = 0; j < SDIM; ++j) {
            int idx = t + 64 - j;
            if (idx > 126) idx -= 127;
            acc += o_s[j] * w_s[idx];
        }
        g_zc[h*SDIM + t] = acc * 64.f;
    }

    int e4 = t & 15, kg = t >> 4;
    int k0 = kh*32 + kg*2;                   // this thread's two k: k0, k0+1

    float4 rv0 = make_float4(0.f,0.f,0.f,0.f), rv1 = rv0;
    float4 ru0 = rv0, ru1 = rv0;

    #pragma unroll
    for (int j = 0; j < SDIM; ++j) {
        float4 vs = vs_s[j*16 + e4];
        float4 us = us_s[j*16 + e4];
        int idx = k0 + 64 - j;               // in [1,126]
        if (idx > 126) idx -= 127;           // (compile-time dead for most j)
        float w0 = w_s[idx];
        float w1 = w_s[idx + 1];             // idx+1 <= 127; w_s[127]==w_s[0]
        rv0.x += vs.x*w0; rv0.y += vs.y*w0; rv0.z += vs.z*w0; rv0.w += vs.w*w0;
        rv1.x += vs.x*w1; rv1.y += vs.y*w1; rv1.z += vs.z*w1; rv1.w += vs.w*w1;
        ru0.x += us.x*w0; ru0.y += us.y*w0; ru0.z += us.z*w0; ru0.w += us.w*w0;
        ru1.x += us.x*w1; ru1.y += us.y*w1; ru1.z += us.z*w1; ru1.w += us.w*w1;
    }

    size_t row0 = ((size_t)(b*SDIM + k0)*HH + h)*(EE/4);
    size_t row1 = row0 + (size_t)HH*(EE/4);
    float4* rv4 = reinterpret_cast<float4*>(g_rv);
    float4* ru4 = reinterpret_cast<float4*>(g_ru);
    rv4[row0 + e4] = rv0;
    rv4[row1 + e4] = rv1;
    ru4[row0 + e4] = ru0;
    ru4[row1 + e4] = ru1;
}

// ---------------------------------------------------------------------------
// Kernel 3: pbv[b, i*64+j, h, e] = RxV[...,j] + RxU[...,i].
// Blocks 0..1023: 8i x 8j tile; RxU rows in registers, each RxV row from L2
// serves 8 output rows; streaming stores for the 256MB write.
// Blocks 1024..1039: z_pb output from g_zc.
// ---------------------------------------------------------------------------
__global__ __launch_bounds__(256) void k_out(float* __restrict__ out) {
    int blk = blockIdx.x;
    int t = threadIdx.x;

    if (blk < 1024) {
        int b = blk >> 6;
        int itile = (blk >> 3) & 7;
        int jt = blk & 7;

        const float4* rub = reinterpret_cast<const float4*>(g_ru + (size_t)b*SDIM*HH*EE)
                          + (size_t)itile*8*(HH*EE/4) + t;
        const float4* rvb = reinterpret_cast<const float4*>(g_rv + (size_t)b*SDIM*HH*EE)
                          + (size_t)jt*8*(HH*EE/4) + t;
        float4* ob = reinterpret_cast<float4*>(out + (size_t)b*SS*HH*EE)
                   + ((size_t)itile*8*SDIM + jt*8)*(HH*EE/4) + t;

        float4 uu[8];
        #pragma unroll
        for (int m = 0; m < 8; ++m)
            uu[m] = __ldg(rub + m*(HH*EE/4));

        #pragma unroll 1
        for (int jj = 0; jj < 8; ++jj) {
            float4 vv = __ldg(rvb + jj*(HH*EE/4));
            #pragma unroll
            for (int m = 0; m < 8; ++m) {
                float4 o;
                o.x = vv.x + uu[m].x; o.y = vv.y + uu[m].y;
                o.z = vv.z + uu[m].z; o.w = vv.w + uu[m].w;
                __stcs(ob + ((size_t)m*SDIM + jj)*(HH*EE/4), o);
            }
        }
    } else {
        int zi = blk - 1024;            // 0..15 -> i = zi*4 .. +3
        __shared__ float zc[HH*SDIM];
        for (int idx = t; idx < HH*SDIM; idx += 256) zc[idx] = g_zc[idx];
        __syncthreads();

        float* o2 = out + (size_t)BB*SS*HH*EE;
        #pragma unroll
        for (int r = 0; r < 4; ++r) {
            int i = zi*4 + r;
            #pragma unroll
            for (int it = 0; it < 4; ++it) {
                int idx = it*256 + t;
                int j = idx >> 4, h = idx & 15;
                o2[(size_t)i*1024 + idx] = zc[h*SDIM + j] + zc[h*SDIM + i];
            }
        }
    }
}

extern "C" void kernel_launch(void* const* d_in, const int* in_sizes, int n_in,
                              void* d_out, int out_size) {
    const float* v  = (const float*)d_in[0];
    const float* w  = (const float*)d_in[1];
    const float* o_ = (const float*)d_in[2];
    float* out = (float*)d_out;

    k_reduce<<<BB*HH*2, 256>>>(v);
    k_conv  <<<BB*HH*2, 256>>>(w, o_);
    k_out   <<<1024 + 16, 256>>>(out);
}

// round 14
// speedup vs baseline: 1.1125x; 1.0206x over previous
#include <cuda_runtime.h>

#define BB 16
#define SS 4096
#define HH 16
#define EE 64
#define SDIM 64
#define NW 127

// Scratch (device globals — no allocation allowed in kernel_launch)
__device__ float g_vs2[2*BB*HH*SDIM*EE]; // [half][b][h][j][e] partial column sums
__device__ float g_us[BB*HH*SDIM*EE];    // [b][h][i][e]       row sums (complete)

// ---------------------------------------------------------------------------
// Kernel 1 (exact R5 config — measured 45-46us, ~75% DRAM):
// Grid = 512: (bh, half). Block covers 32 i. 16 LDG.128/thread per 8-j chunk;
// half-warp pairs combine column partials via shfl_down(16); double-buffered
// 2x16KB stage, ONE barrier per chunk, reducer half alternates so the other
// half issues the next chunk's loads immediately. Row sums stay in registers.
// ---------------------------------------------------------------------------
__global__ __launch_bounds__(256) void k_reduce(const float* __restrict__ v) {
    int bid = blockIdx.x;
    int bh = bid >> 1, half = bid & 1;
    int b = bh >> 4, h = bh & 15;
    int t = threadIdx.x;
    int e4 = t & 15, sub = (t >> 4) & 1, w = t >> 5;

    __shared__ float4 stage[2][8*8*16];   // [buf][w*8+jj][e4]  2 x 16KB

    const float4* v4 = reinterpret_cast<const float4*>(v)
                     + (size_t)b*SS*(HH*EE/4) + h*(EE/4) + e4;

    int i0 = half*32 + w*4 + sub*2;
    float4 crow0 = make_float4(0.f,0.f,0.f,0.f);
    float4 crow1 = make_float4(0.f,0.f,0.f,0.f);

    float* vs_dst = g_vs2 + (size_t)(half*BB*HH + bh)*SDIM*EE;

    #pragma unroll 1
    for (int jc = 0; jc < 8; ++jc) {
        float4 vloc[8];
        const float4* p0 = v4 + (size_t)(i0*SDIM + jc*8)*(HH*EE/4);
        const float4* p1 = p0 + (size_t)SDIM*(HH*EE/4);
        #pragma unroll
        for (int jj = 0; jj < 8; ++jj) {
            float4 a = __ldcs(p0 + (size_t)jj*(HH*EE/4));
            float4 c = __ldcs(p1 + (size_t)jj*(HH*EE/4));
            crow0.x += a.x; crow0.y += a.y; crow0.z += a.z; crow0.w += a.w;
            crow1.x += c.x; crow1.y += c.y; crow1.z += c.z; crow1.w += c.w;
            vloc[jj] = make_float4(a.x + c.x, a.y + c.y, a.z + c.z, a.w + c.w);
        }
        // combine the two half-warps (sub 0/1 hold different i-pairs, same j/e)
        #pragma unroll
        for (int jj = 0; jj < 8; ++jj) {
            vloc[jj].x += __shfl_down_sync(0xffffffffu, vloc[jj].x, 16);
            vloc[jj].y += __shfl_down_sync(0xffffffffu, vloc[jj].y, 16);
            vloc[jj].z += __shfl_down_sync(0xffffffffu, vloc[jj].z, 16);
            vloc[jj].w += __shfl_down_sync(0xffffffffu, vloc[jj].w, 16);
        }
        if (sub == 0) {
            #pragma unroll
            for (int jj = 0; jj < 8; ++jj)
                stage[jc & 1][(w*8 + jj)*16 + e4] = vloc[jj];
        }
        __syncthreads();

        // Alternate which half reduces; the other half issues next-chunk loads.
        bool lower = (t < 128);
        if (lower == ((jc & 1) == 0)) {
            int tt = t & 127;
            int jj = tt >> 4, ee = tt & 15;
            float4 s = stage[jc & 1][jj*16 + ee];
            #pragma unroll
            for (int ww = 1; ww < 8; ++ww) {
                float4 x = stage[jc & 1][(ww*8 + jj)*16 + ee];
                s.x += x.x; s.y += x.y; s.z += x.z; s.w += x.w;
            }
            reinterpret_cast<float4*>(vs_dst + (jc*8 + jj)*EE)[ee] = s;
        }
    }

    // Row sums (complete: thread covered all 64 j for its 2 i's).
    float4* us4 = reinterpret_cast<float4*>(g_us + (size_t)bh*SDIM*EE);
    us4[(i0    )*(EE/4) + e4] = crow0;
    us4[(i0 + 1)*(EE/4) + e4] = crow1;
}

// ---------------------------------------------------------------------------
// Kernel 2: conv + output, fused by redundant compute (no inter-block sync).
// Blocks 0..1023: (bh, q). Each block:
//   1. loads vs/us for its (b,h) into smem (48KB from L2, shared 4-ways),
//   2. computes the FULL 64-k circular convolutions in registers
//      (thread = (e4, kg): 4 k x 4 e x {rv,ru} tile; w padded so no wrap
//      branch; 2048 FMA/thread ~ cheap, 4x redundant by design),
//   3. re-parks rv/ru into the same smem (inputs dead; registers bridged),
//   4. streams its 16-i-row quarter of pbv (256KB) with __stcs.
// Blocks 1024..1039: self-contained z_pb writers (recompute the tiny o_ conv
// locally -- 64K FMA -- then write 4 i-rows each).
// ---------------------------------------------------------------------------
__global__ __launch_bounds__(256) void k_convout(const float* __restrict__ w,
                                                 const float* __restrict__ o_,
                                                 float* __restrict__ out) {
    int blk = blockIdx.x;
    int t = threadIdx.x;

    if (blk < 1024) {
        int bh = blk >> 2, q = blk & 3;
        int b = bh >> 4, h = bh & 15;
        int e4 = t & 15, kg = t >> 4;

        __shared__ float4 vs_s[SDIM*16];   // [j][e4]; becomes rv_s after conv
        __shared__ float4 us_s[SDIM*16];   // [i][e4]; becomes ru_s after conv
        __shared__ float w_s[NW+1];

        const size_t base = (size_t)bh*SDIM*EE;
        const size_t slice4 = (size_t)BB*HH*SDIM*EE/4;
        {
            const float4* pa = reinterpret_cast<const float4*>(g_vs2 + base);
            const float4* pu = reinterpret_cast<const float4*>(g_us + base);
            #pragma unroll
            for (int r = 0; r < 4; ++r) {
                int idx = r*256 + t;
                float4 x = __ldg(pa + idx), y = __ldg(pa + slice4 + idx);
                vs_s[idx] = make_float4(x.x+y.x, x.y+y.y, x.z+y.z, x.w+y.w);
                us_s[idx] = __ldg(pu + idx);
            }
        }
        if (t < NW) w_s[t] = w[h*NW + t];
        if (t == NW) w_s[NW] = w[h*NW];      // pad: w_s[127] = w_s[0]
        __syncthreads();

        // conv in registers: k = kg*4 + kk
        float4 rv[4], ru[4];
        #pragma unroll
        for (int kk = 0; kk < 4; ++kk) {
            rv[kk] = make_float4(0.f,0.f,0.f,0.f);
            ru[kk] = make_float4(0.f,0.f,0.f,0.f);
        }
        int k0 = kg*4;
        #pragma unroll
        for (int j = 0; j < SDIM; ++j) {
            float4 vs = vs_s[j*16 + e4];
            float4 us = us_s[j*16 + e4];
            int idx0 = k0 + 64 - j;          // [k0+1, k0+64], +3 <= 127
            #pragma unroll
            for (int kk = 0; kk < 4; ++kk) {
                float wk = w_s[idx0 + kk];
                rv[kk].x += vs.x*wk; rv[kk].y += vs.y*wk;
                rv[kk].z += vs.z*wk; rv[kk].w += vs.w*wk;
                ru[kk].x += us.x*wk; ru[kk].y += us.y*wk;
                ru[kk].z += us.z*wk; ru[kk].w += us.w*wk;
            }
        }
        __syncthreads();    // inputs dead; reuse smem for rv/ru
        #pragma unroll
        for (int kk = 0; kk < 4; ++kk) {
            vs_s[(k0 + kk)*16 + e4] = rv[kk];   // rv_s
            us_s[(k0 + kk)*16 + e4] = ru[kk];   // ru_s
        }
        __syncthreads();

        // write this quarter's 16 i-rows: out[b, i*64+j, h, e]
        int jg = kg;                          // thread's 4-j group
        float4* out4 = reinterpret_cast<float4*>(out)
                     + (size_t)b*SS*(HH*EE/4) + h*(EE/4) + e4;
        #pragma unroll 1
        for (int ii = 0; ii < 16; ++ii) {
            int i = q*16 + ii;
            float4 ruv = us_s[i*16 + e4];
            float4* orow = out4 + (size_t)(i*SDIM + jg*4)*(HH*EE/4);
            #pragma unroll
            for (int jj = 0; jj < 4; ++jj) {
                float4 rvv = vs_s[(jg*4 + jj)*16 + e4];
                float4 o;
                o.x = rvv.x + ruv.x; o.y = rvv.y + ruv.y;
                o.z = rvv.z + ruv.z; o.w = rvv.w + ruv.w;
                __stcs(orow + (size_t)jj*(HH*EE/4), o);
            }
        }
    } else {
        // ----- self-contained z_pb writers -----
        int zi = blk - 1024;                 // 0..15 -> i = zi*4 .. +3
        __shared__ float w_s2[HH*(NW+1)];
        __shared__ float o_s[SDIM];
        __shared__ float zc[HH*SDIM];

        for (int idx = t; idx < HH*NW; idx += 256) {
            int hh = idx / NW, kk = idx % NW;
            w_s2[hh*(NW+1) + kk] = w[idx];
        }
        if (t < HH) w_s2[t*(NW+1) + NW] = w[t*NW];   // pad per h
        if (t >= 32 && t < 32 + SDIM) o_s[t - 32] = o_[t - 32];
        __syncthreads();

        // zc[h][k] = 64 * sum_j o[j] * w[h][(k-j+64)%127]; 4 outputs/thread
        #pragma unroll
        for (int r = 0; r < 4; ++r) {
            int idx = r*256 + t;             // 0..1023 = h*64 + k
            int hh = idx >> 6, k = idx & 63;
            float acc = 0.f;
            #pragma unroll
            for (int j = 0; j < SDIM; ++j)
                acc += o_s[j] * w_s2[hh*(NW+1) + (k + 64 - j)];
            zc[hh*SDIM + k] = acc * 64.f;
        }
        __syncthreads();

        float* o2 = out + (size_t)BB*SS*HH*EE;
        #pragma unroll
        for (int r = 0; r < 4; ++r) {
            int i = zi*4 + r;
            #pragma unroll
            for (int it = 0; it < 4; ++it) {
                int idx = it*256 + t;        // 0..1023
                int j = idx >> 4, hh = idx & 15;
                o2[(size_t)i*1024 + idx] = zc[hh*SDIM + j] + zc[hh*SDIM + i];
            }
        }
    }
}

extern "C" void kernel_launch(void* const* d_in, const int* in_sizes, int n_in,
                              void* d_out, int out_size) {
    const float* v  = (const float*)d_in[0];
    const float* w  = (const float*)d_in[1];
    const float* o_ = (const float*)d_in[2];
    float* out = (float*)d_out;

    k_reduce <<<BB*HH*2, 256>>>(v);
    k_convout<<<1024 + 16, 256>>>(w, o_, out);
}

// round 15
// speedup vs baseline: 1.1806x; 1.0612x over previous
#include <cuda_runtime.h>

#define BB 16
#define SS 4096
#define HH 16
#define EE 64
#define SDIM 64
#define NW 127

// Scratch (device globals — no allocation allowed in kernel_launch)
__device__ float g_vs2[2*BB*HH*SDIM*EE]; // [half][b][h][j][e] partial column sums
__device__ float g_us[BB*HH*SDIM*EE];    // [b][h][i][e]       row sums (complete)

// ---------------------------------------------------------------------------
// Kernel 1 (exact R5 config — measured 45-46us, ~75% DRAM):
// Grid = 512: (bh, half). Block covers 32 i. 16 LDG.128/thread per 8-j chunk;
// half-warp pairs combine column partials via shfl_down(16); double-buffered
// 2x16KB stage, ONE barrier per chunk, reducer half alternates so the other
// half issues the next chunk's loads immediately. Row sums stay in registers.
// ---------------------------------------------------------------------------
__global__ __launch_bounds__(256) void k_reduce(const float* __restrict__ v) {
    int bid = blockIdx.x;
    int bh = bid >> 1, half = bid & 1;
    int b = bh >> 4, h = bh & 15;
    int t = threadIdx.x;
    int e4 = t & 15, sub = (t >> 4) & 1, w = t >> 5;

    __shared__ float4 stage[2][8*8*16];   // [buf][w*8+jj][e4]  2 x 16KB

    const float4* v4 = reinterpret_cast<const float4*>(v)
                     + (size_t)b*SS*(HH*EE/4) + h*(EE/4) + e4;

    int i0 = half*32 + w*4 + sub*2;
    float4 crow0 = make_float4(0.f,0.f,0.f,0.f);
    float4 crow1 = make_float4(0.f,0.f,0.f,0.f);

    float* vs_dst = g_vs2 + (size_t)(half*BB*HH + bh)*SDIM*EE;

    #pragma unroll 1
    for (int jc = 0; jc < 8; ++jc) {
        float4 vloc[8];
        const float4* p0 = v4 + (size_t)(i0*SDIM + jc*8)*(HH*EE/4);
        const float4* p1 = p0 + (size_t)SDIM*(HH*EE/4);
        #pragma unroll
        for (int jj = 0; jj < 8; ++jj) {
            float4 a = __ldcs(p0 + (size_t)jj*(HH*EE/4));
            float4 c = __ldcs(p1 + (size_t)jj*(HH*EE/4));
            crow0.x += a.x; crow0.y += a.y; crow0.z += a.z; crow0.w += a.w;
            crow1.x += c.x; crow1.y += c.y; crow1.z += c.z; crow1.w += c.w;
            vloc[jj] = make_float4(a.x + c.x, a.y + c.y, a.z + c.z, a.w + c.w);
        }
        // combine the two half-warps (sub 0/1 hold different i-pairs, same j/e)
        #pragma unroll
        for (int jj = 0; jj < 8; ++jj) {
            vloc[jj].x += __shfl_down_sync(0xffffffffu, vloc[jj].x, 16);
            vloc[jj].y += __shfl_down_sync(0xffffffffu, vloc[jj].y, 16);
            vloc[jj].z += __shfl_down_sync(0xffffffffu, vloc[jj].z, 16);
            vloc[jj].w += __shfl_down_sync(0xffffffffu, vloc[jj].w, 16);
        }
        if (sub == 0) {
            #pragma unroll
            for (int jj = 0; jj < 8; ++jj)
                stage[jc & 1][(w*8 + jj)*16 + e4] = vloc[jj];
        }
        __syncthreads();

        // Alternate which half reduces; the other half issues next-chunk loads.
        bool lower = (t < 128);
        if (lower == ((jc & 1) == 0)) {
            int tt = t & 127;
            int jj = tt >> 4, ee = tt & 15;
            float4 s = stage[jc & 1][jj*16 + ee];
            #pragma unroll
            for (int ww = 1; ww < 8; ++ww) {
                float4 x = stage[jc & 1][(ww*8 + jj)*16 + ee];
                s.x += x.x; s.y += x.y; s.z += x.z; s.w += x.w;
            }
            reinterpret_cast<float4*>(vs_dst + (jc*8 + jj)*EE)[ee] = s;
        }
    }

    // Row sums (complete: thread covered all 64 j for its 2 i's).
    float4* us4 = reinterpret_cast<float4*>(g_us + (size_t)bh*SDIM*EE);
    us4[(i0    )*(EE/4) + e4] = crow0;
    us4[(i0 + 1)*(EE/4) + e4] = crow1;
}

// ---------------------------------------------------------------------------
// Kernel 2: conv + output, fused by (minimized) redundant compute.
// Blocks 0..1023: (bh, q). Each block:
//   1. loads vs/us partials for its (b,h) into smem (48KB, L2-hot, x4 shared),
//   2. conv: rv at ALL 64 k (needed for every j it writes; thread (e4,kg)
//      owns 4 k -> 1024 FMA) and ru ONLY at its 16 i-rows (thread (e4,g)
//      owns 1 i -> 256 FMA). 1280 FMA/thread vs 2048 before.
//   3. rv re-parks into vs_s (registers bridge); ru goes to a separate 4KB
//      ru_s (no aliasing with the us_s it reads).
//   4. streams its 16-i-row quarter of pbv (256KB) with __stcs.
// 4 blocks/SM via launch_bounds (regs<=64, smem ~37KB).
// Blocks 1024..1039: self-contained z_pb writers.
// ---------------------------------------------------------------------------
__global__ __launch_bounds__(256, 4) void k_convout(const float* __restrict__ w,
                                                    const float* __restrict__ o_,
                                                    float* __restrict__ out) {
    int blk = blockIdx.x;
    int t = threadIdx.x;

    if (blk < 1024) {
        int bh = blk >> 2, q = blk & 3;
        int b = bh >> 4, h = bh & 15;
        int e4 = t & 15, kg = t >> 4;      // kg also serves as g and jg

        __shared__ float4 vs_s[SDIM*16];   // [j][e4]; becomes rv_s after conv
        __shared__ float4 us_s[SDIM*16];   // [i][e4]  (stays input)
        __shared__ float4 ru_s[16*16];     // [i_local][e4]
        __shared__ float w_s[NW+1];

        const size_t base = (size_t)bh*SDIM*EE;
        const size_t slice4 = (size_t)BB*HH*SDIM*EE/4;
        {
            const float4* pa = reinterpret_cast<const float4*>(g_vs2 + base);
            const float4* pu = reinterpret_cast<const float4*>(g_us + base);
            #pragma unroll
            for (int r = 0; r < 4; ++r) {
                int idx = r*256 + t;
                float4 x = __ldg(pa + idx), y = __ldg(pa + slice4 + idx);
                vs_s[idx] = make_float4(x.x+y.x, x.y+y.y, x.z+y.z, x.w+y.w);
                us_s[idx] = __ldg(pu + idx);
            }
        }
        if (t < NW) w_s[t] = w[h*NW + t];
        if (t == NW) w_s[NW] = w[h*NW];      // pad: w_s[127] = w_s[0]
        __syncthreads();

        // --- rv conv: all 64 k; thread owns k = kg*4 + kk ---
        float4 rv[4];
        #pragma unroll
        for (int kk = 0; kk < 4; ++kk) rv[kk] = make_float4(0.f,0.f,0.f,0.f);
        int k0 = kg*4;
        #pragma unroll
        for (int j = 0; j < SDIM; ++j) {
            float4 vs = vs_s[j*16 + e4];
            int idx0 = k0 + 64 - j;          // [k0+1, k0+64], +3 <= 127
            #pragma unroll
            for (int kk = 0; kk < 4; ++kk) {
                float wk = w_s[idx0 + kk];
                rv[kk].x += vs.x*wk; rv[kk].y += vs.y*wk;
                rv[kk].z += vs.z*wk; rv[kk].w += vs.w*wk;
            }
        }

        // --- ru conv: only this quarter's 16 i-rows; thread owns i = q*16+kg ---
        float4 ru = make_float4(0.f,0.f,0.f,0.f);
        {
            int ii = q*16 + kg;
            #pragma unroll
            for (int j = 0; j < SDIM; ++j) {
                float us0 = 0.f;   // placeholder to keep FMA shape tight
                float4 us = us_s[j*16 + e4];
                float wk = w_s[ii + 64 - j];
                (void)us0;
                ru.x += us.x*wk; ru.y += us.y*wk;
                ru.z += us.z*wk; ru.w += us.w*wk;
            }
            ru_s[kg*16 + e4] = ru;
        }

        __syncthreads();    // vs_s reads done; reuse for rv
        #pragma unroll
        for (int kk = 0; kk < 4; ++kk)
            vs_s[(k0 + kk)*16 + e4] = rv[kk];
        __syncthreads();

        // write this quarter's 16 i-rows: out[b, i*64+j, h, e]
        float4* out4 = reinterpret_cast<float4*>(out)
                     + (size_t)b*SS*(HH*EE/4) + h*(EE/4) + e4;
        #pragma unroll 1
        for (int ii = 0; ii < 16; ++ii) {
            int i = q*16 + ii;
            float4 ruv = ru_s[ii*16 + e4];
            float4* orow = out4 + (size_t)(i*SDIM + kg*4)*(HH*EE/4);
            #pragma unroll
            for (int jj = 0; jj < 4; ++jj) {
                float4 rvv = vs_s[(kg*4 + jj)*16 + e4];
                float4 o;
                o.x = rvv.x + ruv.x; o.y = rvv.y + ruv.y;
                o.z = rvv.z + ruv.z; o.w = rvv.w + ruv.w;
                __stcs(orow + (size_t)jj*(HH*EE/4), o);
            }
        }
    } else {
        // ----- self-contained z_pb writers -----
        int zi = blk - 1024;                 // 0..15 -> i = zi*4 .. +3
        __shared__ float w_s2[HH*(NW+1)];
        __shared__ float o_s[SDIM];
        __shared__ float zc[HH*SDIM];

        for (int idx = t; idx < HH*NW; idx += 256) {
            int hh = idx / NW, kk = idx % NW;
            w_s2[hh*(NW+1) + kk] = w[idx];
        }
        if (t < HH) w_s2[t*(NW+1) + NW] = w[t*NW];   // pad per h
        if (t >= 32 && t < 32 + SDIM) o_s[t - 32] = o_[t - 32];
        __syncthreads();

        // zc[h][k] = 64 * sum_j o[j] * w[h][(k-j+64)%127]; 4 outputs/thread
        #pragma unroll
        for (int r = 0; r < 4; ++r) {
            int idx = r*256 + t;             // 0..1023 = h*64 + k
            int hh = idx >> 6, k = idx & 63;
            float acc = 0.f;
            #pragma unroll
            for (int j = 0; j < SDIM; ++j)
                acc += o_s[j] * w_s2[hh*(NW+1) + (k + 64 - j)];
            zc[hh*SDIM + k] = acc * 64.f;
        }
        __syncthreads();

        float* o2 = out + (size_t)BB*SS*HH*EE;
        #pragma unroll
        for (int r = 0; r < 4; ++r) {
            int i = zi*4 + r;
            #pragma unroll
            for (int it = 0; it < 4; ++it) {
                int idx = it*256 + t;        // 0..1023
                int j = idx >> 4, hh = idx & 15;
                o2[(size_t)i*1024 + idx] = zc[hh*SDIM + j] + zc[hh*SDIM + i];
            }
        }
    }
}

extern "C" void kernel_launch(void* const* d_in, const int* in_sizes, int n_in,
                              void* d_out, int out_size) {
    const float* v  = (const float*)d_in[0];
    const float* w  = (const float*)d_in[1];
    const float* o_ = (const float*)d_in[2];
    float* out = (float*)d_out;

    k_reduce <<<BB*HH*2, 256>>>(v);
    k_convout<<<1024 + 16, 256>>>(w, o_, out);
}